// round 12
// baseline (speedup 1.0000x reference)
#include <cuda_runtime.h>
#include <cuda_fp16.h>

#define NNODES 20000
#define NEDGES 640000
#define HD 128
#define DD 64
#define LL 4
#define NPART 20          // ceil(NNODES/1024)
#define AS 72             // As stride in halves (144B rows)
#define BS 68             // Bt stride in halves (136B rows)
#define CVT_BLOCKS 1250   // NNODES*16 float4s / 256
#define HIST_BLOCKS 625   // NEDGES/4 int4s / 256

// ---------------- static device scratch (zero-initialized) ----------------
__device__ __half g_xl[NNODES * HD];
__device__ __half g_xr[NNODES * HD];
__device__ __half g_xa[NNODES * DD];
__device__ __half g_xb[NNODES * DD];
__device__ int    g_rowptr[NNODES + 1];
__device__ int    g_deg[NNODES];      // invariant: zero at entry to k_cvt_hist
__device__ int    g_cursor[NNODES];   // invariant: zero at entry to k_scatter
__device__ int    g_csr_src[NEDGES];
__device__ int    g_part[32];

__device__ __forceinline__ const __half* hin(int s)  { return s ? g_xb : g_xa; }
__device__ __forceinline__ __half*       hout(int s) { return s ? g_xb : g_xa; }

// ---------------- fused: pert fp32 -> g_xa fp16  +  degree histogram ----------------
__global__ void k_cvt_hist(const float* __restrict__ pert, const int* __restrict__ dst) {
    int b = blockIdx.x;
    if (b < CVT_BLOCKS) {
        int i = b * 256 + threadIdx.x;
        if (i < NNODES * 16) {
            float4 v = ((const float4*)pert)[i];
            __half2 h0 = __floats2half2_rn(v.x, v.y);
            __half2 h1 = __floats2half2_rn(v.z, v.w);
            uint2 pk;
            pk.x = *(unsigned*)&h0; pk.y = *(unsigned*)&h1;
            ((uint2*)g_xa)[i] = pk;
        }
    } else {
        int i = (b - CVT_BLOCKS) * 256 + threadIdx.x;
        if (i < NEDGES / 4) {
            int4 d = ((const int4*)dst)[i];
            atomicAdd(&g_deg[d.x], 1);
            atomicAdd(&g_deg[d.y], 1);
            atomicAdd(&g_deg[d.z], 1);
            atomicAdd(&g_deg[d.w], 1);
        }
    }
}

// ---------------- CSR scan: warp-shfl two-level partial scan; re-zeroes deg & cursor ----------------
__global__ void k_scan_part() {
    __shared__ int wtot[32];
    int b = blockIdx.x, t = threadIdx.x;
    int lane = t & 31, w = t >> 5;
    int i = b * 1024 + t;
    int v = 0;
    if (i < NNODES) {
        v = g_deg[i];
        g_deg[i] = 0;        // restore invariant for next launch
        g_cursor[i] = 0;     // ready for scatter
    }
    int x = v;
#pragma unroll
    for (int off = 1; off < 32; off <<= 1) {
        int u = __shfl_up_sync(0xffffffffu, x, off);
        if (lane >= off) x += u;
    }
    if (lane == 31) wtot[w] = x;
    __syncthreads();
    if (w == 0) {
        int y = wtot[lane];
#pragma unroll
        for (int off = 1; off < 32; off <<= 1) {
            int u = __shfl_up_sync(0xffffffffu, y, off);
            if (lane >= off) y += u;
        }
        wtot[lane] = y;
    }
    __syncthreads();
    int incl = x + (w > 0 ? wtot[w - 1] : 0);
    if (i < NNODES) g_rowptr[i + 1] = incl;
    if (t == 1023) g_part[b] = incl;   // block total
}

// fused top-scan + add: each block computes its own exclusive prefix over g_part
__global__ void k_scan_add() {
    __shared__ int off_sh;
    int b = blockIdx.x, t = threadIdx.x;
    if (t == 0) {
        int o = 0;
        for (int j = 0; j < b; j++) o += g_part[j];
        off_sh = o;
    }
    __syncthreads();
    int i = b * 1024 + t;
    if (b > 0 && i < NNODES) g_rowptr[i + 1] += off_sh;
    if (b == 0 && t == 0) g_rowptr[0] = 0;
}

// vectorized scatter: 4 independent atomic->store chains per thread
__global__ void k_scatter(const int* __restrict__ src, const int* __restrict__ dst) {
    int i = blockIdx.x * blockDim.x + threadIdx.x;
    if (i < NEDGES / 4) {
        int4 d = ((const int4*)dst)[i];
        int4 sv = ((const int4*)src)[i];
        int r0 = g_rowptr[d.x], r1 = g_rowptr[d.y];
        int r2 = g_rowptr[d.z], r3 = g_rowptr[d.w];
        int p0 = r0 + atomicAdd(&g_cursor[d.x], 1);
        int p1 = r1 + atomicAdd(&g_cursor[d.y], 1);
        int p2 = r2 + atomicAdd(&g_cursor[d.z], 1);
        int p3 = r3 + atomicAdd(&g_cursor[d.w], 1);
        g_csr_src[p0] = sv.x;
        g_csr_src[p1] = sv.y;
        g_csr_src[p2] = sv.z;
        g_csr_src[p3] = sv.w;
    }
}

// ---------------- mma helper ----------------
__device__ __forceinline__ void mma16816(float* c, unsigned a0, unsigned a1,
                                         unsigned a2, unsigned a3,
                                         unsigned b0, unsigned b1) {
    asm volatile(
        "mma.sync.aligned.m16n8k16.row.col.f32.f16.f16.f32 "
        "{%0,%1,%2,%3}, {%4,%5,%6,%7}, {%8,%9}, {%0,%1,%2,%3};\n"
        : "+f"(c[0]), "+f"(c[1]), "+f"(c[2]), "+f"(c[3])
        : "r"(a0), "r"(a1), "r"(a2), "r"(a3), "r"(b0), "r"(b1));
}

// ---------------- xl/xr GEMM (tensor core): 128-row tiles, 256 threads ----------------
__global__ __launch_bounds__(256) void k_gemm_lr(
    int insel,
    const float* __restrict__ Wl, const float* __restrict__ Wr,
    const float* __restrict__ bl, const float* __restrict__ br)
{
    __shared__ __half As[128 * AS];
    __shared__ __half Bt[64 * BS];   // Bt[n_local][k]
    const __half* x = hin(insel);
    int tid = threadIdx.x, wid = tid >> 5, lane = tid & 31;
    int m0 = blockIdx.x * 128;
    int c0 = blockIdx.y * 64;
    bool isL = (c0 < HD);
    const float* W  = isL ? Wl : Wr;
    const float* bv = isL ? bl : br;
    int wc0 = c0 & (HD - 1);

    for (int i = tid; i < 1024; i += 256) {
        int r = i >> 3, c8 = i & 7;
        int row = m0 + r;
        uint4 v = make_uint4(0u, 0u, 0u, 0u);
        if (row < NNODES) v = ((const uint4*)x)[row * 8 + c8];
        *(uint4*)&As[r * AS + c8 * 8] = v;
    }
    for (int i = tid; i < 1024; i += 256) {
        int k = i >> 4, c4 = i & 15;
        float4 v = *(const float4*)&W[k * HD + wc0 + c4 * 4];
        Bt[(c4 * 4 + 0) * BS + k] = __float2half_rn(v.x);
        Bt[(c4 * 4 + 1) * BS + k] = __float2half_rn(v.y);
        Bt[(c4 * 4 + 2) * BS + k] = __float2half_rn(v.z);
        Bt[(c4 * 4 + 3) * BS + k] = __float2half_rn(v.w);
    }
    __syncthreads();

    float acc[8][4];
#pragma unroll
    for (int nt = 0; nt < 8; nt++)
#pragma unroll
        for (int j = 0; j < 4; j++) acc[nt][j] = 0.f;

    int r0 = wid * 16 + (lane >> 2);
    int kc = (lane & 3) * 2;
    int nb = lane >> 2;
#pragma unroll
    for (int ks = 0; ks < 4; ks++) {
        unsigned a0 = *(const unsigned*)&As[r0 * AS + ks * 16 + kc];
        unsigned a1 = *(const unsigned*)&As[(r0 + 8) * AS + ks * 16 + kc];
        unsigned a2 = *(const unsigned*)&As[r0 * AS + ks * 16 + kc + 8];
        unsigned a3 = *(const unsigned*)&As[(r0 + 8) * AS + ks * 16 + kc + 8];
#pragma unroll
        for (int nt = 0; nt < 8; nt++) {
            unsigned b0 = *(const unsigned*)&Bt[(nt * 8 + nb) * BS + ks * 16 + kc];
            unsigned b1 = *(const unsigned*)&Bt[(nt * 8 + nb) * BS + ks * 16 + kc + 8];
            mma16816(acc[nt], a0, a1, a2, a3, b0, b1);
        }
    }

    __half* out = isL ? g_xl : g_xr;
    int colb = (lane & 3) * 2;
    int rowA = m0 + wid * 16 + (lane >> 2);
#pragma unroll
    for (int nt = 0; nt < 8; nt++) {
        int c = wc0 + nt * 8 + colb;
        float bias0 = bv[c], bias1 = bv[c + 1];
        if (rowA < NNODES) {
            __half2 h = __floats2half2_rn(acc[nt][0] + bias0, acc[nt][1] + bias1);
            *(__half2*)&out[rowA * HD + c] = h;
        }
        if (rowA + 8 < NNODES) {
            __half2 h = __floats2half2_rn(acc[nt][2] + bias0, acc[nt][3] + bias1);
            *(__half2*)&out[(rowA + 8) * HD + c] = h;
        }
    }
}

// ---------------- GATv2 attention: 1 warp/node, 2 slots x 4 edges/iter (MLP=4) ----------------
__global__ void k_attn(const float* __restrict__ att, const float* __restrict__ bias,
                       int outsel)
{
    int n = (blockIdx.x * blockDim.x + threadIdx.x) >> 5;
    int lane = threadIdx.x & 31;
    if (n >= NNODES) return;
    int q = lane & 15, slot = lane >> 4;

    uint4 rr = ((const uint4*)g_xr)[n * 16 + q];
    __half2 r0 = *(__half2*)&rr.x, r1 = *(__half2*)&rr.y;
    __half2 r2 = *(__half2*)&rr.z, r3 = *(__half2*)&rr.w;

    float4 af0 = ((const float4*)att)[q * 2];
    float4 af1 = ((const float4*)att)[q * 2 + 1];
    __half2 a0 = __floats2half2_rn(af0.x, af0.y), a1 = __floats2half2_rn(af0.z, af0.w);
    __half2 a2 = __floats2half2_rn(af1.x, af1.y), a3 = __floats2half2_rn(af1.z, af1.w);
    const __half2 c02 = __floats2half2_rn(0.2f, 0.2f);

    float s = 0.f;
    float o0 = 0.f, o1 = 0.f, o2 = 0.f, o3 = 0.f, o4 = 0.f, o5 = 0.f, o6 = 0.f, o7 = 0.f;

    int beg = g_rowptr[n], end = g_rowptr[n + 1];
    int deg = end - beg;
    int niter = (deg + 7) >> 3;          // uniform across the warp (8 edges / iter)

    for (int j = 0; j < niter; j++) {
        int p = beg + slot + j * 8;
        bool vld[4];
        int  si[4];
        uint4 u[4];
#pragma unroll
        for (int ii = 0; ii < 4; ii++) {
            int e = p + ii * 2;
            vld[ii] = e < end;
            si[ii] = g_csr_src[vld[ii] ? e : beg];
        }
#pragma unroll
        for (int ii = 0; ii < 4; ii++)
            u[ii] = ((const uint4*)g_xl)[si[ii] * 16 + q];

#pragma unroll
        for (int ii = 0; ii < 4; ii++) {
            __half2 v0 = *(__half2*)&u[ii].x, v1 = *(__half2*)&u[ii].y;
            __half2 v2 = *(__half2*)&u[ii].z, v3 = *(__half2*)&u[ii].w;

            __half2 e0 = __hadd2(v0, r0), e1 = __hadd2(v1, r1);
            __half2 e2 = __hadd2(v2, r2), e3 = __hadd2(v3, r3);
            __half2 l0 = __hmax2(e0, __hmul2(e0, c02));
            __half2 l1 = __hmax2(e1, __hmul2(e1, c02));
            __half2 l2 = __hmax2(e2, __hmul2(e2, c02));
            __half2 l3 = __hmax2(e3, __hmul2(e3, c02));
            __half2 d  = __hmul2(l0, a0);
            d = __hfma2(l1, a1, d);
            d = __hfma2(l2, a2, d);
            d = __hfma2(l3, a3, d);
            float part = __low2float(d) + __high2float(d);
            part += __shfl_xor_sync(0xffffffffu, part, 1);
            part += __shfl_xor_sync(0xffffffffu, part, 2);
            part += __shfl_xor_sync(0xffffffffu, part, 4);
            float w = vld[ii] ? __expf(part) : 0.f;
            s += w;
            float2 f0 = __half22float2(v0), f1 = __half22float2(v1);
            float2 f2 = __half22float2(v2), f3 = __half22float2(v3);
            o0 = fmaf(w, f0.x, o0); o1 = fmaf(w, f0.y, o1);
            o2 = fmaf(w, f1.x, o2); o3 = fmaf(w, f1.y, o3);
            o4 = fmaf(w, f2.x, o4); o5 = fmaf(w, f2.y, o5);
            o6 = fmaf(w, f3.x, o6); o7 = fmaf(w, f3.y, o7);
        }
    }

    s  += __shfl_xor_sync(0xffffffffu, s, 16);
    o0 += __shfl_xor_sync(0xffffffffu, o0, 16);
    o1 += __shfl_xor_sync(0xffffffffu, o1, 16);
    o2 += __shfl_xor_sync(0xffffffffu, o2, 16);
    o3 += __shfl_xor_sync(0xffffffffu, o3, 16);
    o4 += __shfl_xor_sync(0xffffffffu, o4, 16);
    o5 += __shfl_xor_sync(0xffffffffu, o5, 16);
    o6 += __shfl_xor_sync(0xffffffffu, o6, 16);
    o7 += __shfl_xor_sync(0xffffffffu, o7, 16);

    float inv = (deg > 0) ? (1.f / s) : 0.f;
    o0 *= inv; o1 *= inv; o2 *= inv; o3 *= inv;
    o4 *= inv; o5 *= inv; o6 *= inv; o7 *= inv;

    o0 = 0.5f * (o0 + __shfl_xor_sync(0xffffffffu, o0, 8));
    o1 = 0.5f * (o1 + __shfl_xor_sync(0xffffffffu, o1, 8));
    o2 = 0.5f * (o2 + __shfl_xor_sync(0xffffffffu, o2, 8));
    o3 = 0.5f * (o3 + __shfl_xor_sync(0xffffffffu, o3, 8));
    o4 = 0.5f * (o4 + __shfl_xor_sync(0xffffffffu, o4, 8));
    o5 = 0.5f * (o5 + __shfl_xor_sync(0xffffffffu, o5, 8));
    o6 = 0.5f * (o6 + __shfl_xor_sync(0xffffffffu, o6, 8));
    o7 = 0.5f * (o7 + __shfl_xor_sync(0xffffffffu, o7, 8));

    if (lane < 8) {
        float4 b0 = ((const float4*)bias)[q * 2];
        float4 b1 = ((const float4*)bias)[q * 2 + 1];
        float t0 = o0 + b0.x; t0 = t0 > 0.f ? t0 : 0.01f * t0;
        float t1 = o1 + b0.y; t1 = t1 > 0.f ? t1 : 0.01f * t1;
        float t2 = o2 + b0.z; t2 = t2 > 0.f ? t2 : 0.01f * t2;
        float t3 = o3 + b0.w; t3 = t3 > 0.f ? t3 : 0.01f * t3;
        float t4 = o4 + b1.x; t4 = t4 > 0.f ? t4 : 0.01f * t4;
        float t5 = o5 + b1.y; t5 = t5 > 0.f ? t5 : 0.01f * t5;
        float t6 = o6 + b1.z; t6 = t6 > 0.f ? t6 : 0.01f * t6;
        float t7 = o7 + b1.w; t7 = t7 > 0.f ? t7 : 0.01f * t7;
        __half2 h0 = __floats2half2_rn(t0, t1);
        __half2 h1 = __floats2half2_rn(t2, t3);
        __half2 h2 = __floats2half2_rn(t4, t5);
        __half2 h3 = __floats2half2_rn(t6, t7);
        uint4 pk;
        pk.x = *(unsigned*)&h0; pk.y = *(unsigned*)&h1;
        pk.z = *(unsigned*)&h2; pk.w = *(unsigned*)&h3;
        ((uint4*)hout(outsel))[n * 8 + q] = pk;
    }
}

// ---------------- final projection (tensor core): 128-row tiles, 256 threads ----------------
__global__ __launch_bounds__(256) void k_gemm_o(
    int insel,
    const float* __restrict__ Wo, const float* __restrict__ bo,
    float* __restrict__ out)
{
    __shared__ __half As[128 * AS];
    __shared__ __half Bt[64 * BS];
    const __half* x = hin(insel);
    int tid = threadIdx.x, wid = tid >> 5, lane = tid & 31;
    int m0 = blockIdx.x * 128;

    for (int i = tid; i < 1024; i += 256) {
        int r = i >> 3, c8 = i & 7;
        int row = m0 + r;
        uint4 v = make_uint4(0u, 0u, 0u, 0u);
        if (row < NNODES) v = ((const uint4*)x)[row * 8 + c8];
        *(uint4*)&As[r * AS + c8 * 8] = v;
    }
    for (int i = tid; i < 1024; i += 256) {
        int k = i >> 4, c4 = i & 15;
        float4 v = *(const float4*)&Wo[k * DD + c4 * 4];
        Bt[(c4 * 4 + 0) * BS + k] = __float2half_rn(v.x);
        Bt[(c4 * 4 + 1) * BS + k] = __float2half_rn(v.y);
        Bt[(c4 * 4 + 2) * BS + k] = __float2half_rn(v.z);
        Bt[(c4 * 4 + 3) * BS + k] = __float2half_rn(v.w);
    }
    __syncthreads();

    float acc[8][4];
#pragma unroll
    for (int nt = 0; nt < 8; nt++)
#pragma unroll
        for (int j = 0; j < 4; j++) acc[nt][j] = 0.f;

    int r0 = wid * 16 + (lane >> 2);
    int kc = (lane & 3) * 2;
    int nb = lane >> 2;
#pragma unroll
    for (int ks = 0; ks < 4; ks++) {
        unsigned a0 = *(const unsigned*)&As[r0 * AS + ks * 16 + kc];
        unsigned a1 = *(const unsigned*)&As[(r0 + 8) * AS + ks * 16 + kc];
        unsigned a2 = *(const unsigned*)&As[r0 * AS + ks * 16 + kc + 8];
        unsigned a3 = *(const unsigned*)&As[(r0 + 8) * AS + ks * 16 + kc + 8];
#pragma unroll
        for (int nt = 0; nt < 8; nt++) {
            unsigned b0 = *(const unsigned*)&Bt[(nt * 8 + nb) * BS + ks * 16 + kc];
            unsigned b1 = *(const unsigned*)&Bt[(nt * 8 + nb) * BS + ks * 16 + kc + 8];
            mma16816(acc[nt], a0, a1, a2, a3, b0, b1);
        }
    }

    int colb = (lane & 3) * 2;
    int rowA = m0 + wid * 16 + (lane >> 2);
#pragma unroll
    for (int nt = 0; nt < 8; nt++) {
        int c = nt * 8 + colb;
        float bias0 = bo[c], bias1 = bo[c + 1];
        if (rowA < NNODES) {
            float t0 = acc[nt][0] + bias0; t0 = t0 > 0.f ? t0 : 0.01f * t0;
            float t1 = acc[nt][1] + bias1; t1 = t1 > 0.f ? t1 : 0.01f * t1;
            *(float2*)&out[rowA * DD + c] = make_float2(t0, t1);
        }
        if (rowA + 8 < NNODES) {
            float t0 = acc[nt][2] + bias0; t0 = t0 > 0.f ? t0 : 0.01f * t0;
            float t1 = acc[nt][3] + bias1; t1 = t1 > 0.f ? t1 : 0.01f * t1;
            *(float2*)&out[(rowA + 8) * DD + c] = make_float2(t0, t1);
        }
    }
}

// ---------------- launch ----------------
extern "C" void kernel_launch(void* const* d_in, const int* in_sizes, int n_in,
                              void* d_out, int out_size)
{
    const int*   ei   = (const int*)d_in[0];
    const float* pert = (const float*)d_in[2];
    const float* Wl   = (const float*)d_in[3];
    const float* bl   = (const float*)d_in[4];
    const float* Wr   = (const float*)d_in[5];
    const float* br   = (const float*)d_in[6];
    const float* att  = (const float*)d_in[7];
    const float* bias = (const float*)d_in[8];
    const float* Wo   = (const float*)d_in[9];
    const float* bo   = (const float*)d_in[10];
    float* out = (float*)d_out;

    const int* src = ei;
    const int* dst = ei + NEDGES;

    k_cvt_hist<<<CVT_BLOCKS + HIST_BLOCKS, 256>>>(pert, dst);
    k_scan_part<<<NPART, 1024>>>();
    k_scan_add<<<NPART, 1024>>>();
    k_scatter<<<(NEDGES / 4 + 255) / 256, 256>>>(src, dst);

    for (int l = 0; l < LL; l++) {
        int insel  = (l & 1);        // 0 = g_xa, 1 = g_xb
        int outsel = insel ^ 1;
        dim3 g((NNODES + 127) / 128, 4);
        k_gemm_lr<<<g, 256>>>(insel,
                              Wl + (size_t)l * DD * HD, Wr + (size_t)l * DD * HD,
                              bl + (size_t)l * HD,      br + (size_t)l * HD);
        k_attn<<<(NNODES * 32 + 255) / 256, 256>>>(att + (size_t)l * HD,
                                                   bias + (size_t)l * DD, outsel);
    }
    // after 4 layers the last output landed in g_xa (layer 3: insel=1 -> outsel=0)
    k_gemm_o<<<(NNODES + 127) / 128, 256>>>(0, Wo, bo, out);
}

// round 17
// speedup vs baseline: 1.0705x; 1.0705x over previous
#include <cuda_runtime.h>
#include <cuda_fp16.h>

#define NNODES 20000
#define NEDGES 640000
#define HD 128
#define DD 64
#define LL 4
#define NPART 20          // ceil(NNODES/1024)
#define AS 72             // As stride in halves (144B rows)
#define BS 68             // Bt stride in halves (136B rows)

// ---------------- static device scratch (zero-initialized) ----------------
__device__ __half g_xl[NNODES * HD];
__device__ __half g_xr[NNODES * HD];
__device__ __half g_xa[NNODES * DD];
__device__ __half g_xb[NNODES * DD];
__device__ int    g_rowptr[NNODES + 1];
__device__ int    g_deg[NNODES];      // invariant: zero at entry to k_hist
__device__ int    g_cursor[NNODES];   // invariant: zero at entry to k_scatter
__device__ int    g_csr_src[NEDGES];
__device__ int    g_part[32];

__device__ __forceinline__ const __half* hin(int s)  { return s ? g_xb : g_xa; }
__device__ __forceinline__ __half*       hout(int s) { return s ? g_xb : g_xa; }

// ---------------- pert fp32 -> g_xa fp16 ----------------
__global__ void k_cvt(const float* __restrict__ pert) {
    int i = blockIdx.x * blockDim.x + threadIdx.x;
    if (i < NNODES * 16) {
        float4 v = ((const float4*)pert)[i];
        __half2 h0 = __floats2half2_rn(v.x, v.y);
        __half2 h1 = __floats2half2_rn(v.z, v.w);
        uint2 pk;
        pk.x = *(unsigned*)&h0; pk.y = *(unsigned*)&h1;
        ((uint2*)g_xa)[i] = pk;
    }
}

// ---------------- degree histogram ----------------
__global__ void k_hist(const int* __restrict__ dst) {
    int i = blockIdx.x * blockDim.x + threadIdx.x;
    if (i < NEDGES / 4) {
        int4 d = ((const int4*)dst)[i];
        atomicAdd(&g_deg[d.x], 1);
        atomicAdd(&g_deg[d.y], 1);
        atomicAdd(&g_deg[d.z], 1);
        atomicAdd(&g_deg[d.w], 1);
    }
}

// ---------------- CSR scan: warp-shfl two-level partial scan; re-zeroes deg & cursor ----------------
__global__ void k_scan_part() {
    __shared__ int wtot[32];
    int b = blockIdx.x, t = threadIdx.x;
    int lane = t & 31, w = t >> 5;
    int i = b * 1024 + t;
    int v = 0;
    if (i < NNODES) {
        v = g_deg[i];
        g_deg[i] = 0;        // restore invariant for next launch
        g_cursor[i] = 0;     // ready for scatter
    }
    int x = v;
#pragma unroll
    for (int off = 1; off < 32; off <<= 1) {
        int u = __shfl_up_sync(0xffffffffu, x, off);
        if (lane >= off) x += u;
    }
    if (lane == 31) wtot[w] = x;
    __syncthreads();
    if (w == 0) {
        int y = wtot[lane];
#pragma unroll
        for (int off = 1; off < 32; off <<= 1) {
            int u = __shfl_up_sync(0xffffffffu, y, off);
            if (lane >= off) y += u;
        }
        wtot[lane] = y;
    }
    __syncthreads();
    int incl = x + (w > 0 ? wtot[w - 1] : 0);
    if (i < NNODES) g_rowptr[i + 1] = incl;
    if (t == 1023) g_part[b] = incl;   // block total
}

// fused top-scan + add
__global__ void k_scan_add() {
    __shared__ int off_sh;
    int b = blockIdx.x, t = threadIdx.x;
    if (t == 0) {
        int o = 0;
        for (int j = 0; j < b; j++) o += g_part[j];
        off_sh = o;
    }
    __syncthreads();
    int i = b * 1024 + t;
    if (b > 0 && i < NNODES) g_rowptr[i + 1] += off_sh;
    if (b == 0 && t == 0) g_rowptr[0] = 0;
}

__global__ void k_scatter(const int* __restrict__ src, const int* __restrict__ dst) {
    int i = blockIdx.x * blockDim.x + threadIdx.x;
    if (i < NEDGES / 4) {
        int4 d = ((const int4*)dst)[i];
        int4 sv = ((const int4*)src)[i];
        int r0 = g_rowptr[d.x], r1 = g_rowptr[d.y];
        int r2 = g_rowptr[d.z], r3 = g_rowptr[d.w];
        int p0 = r0 + atomicAdd(&g_cursor[d.x], 1);
        int p1 = r1 + atomicAdd(&g_cursor[d.y], 1);
        int p2 = r2 + atomicAdd(&g_cursor[d.z], 1);
        int p3 = r3 + atomicAdd(&g_cursor[d.w], 1);
        g_csr_src[p0] = sv.x;
        g_csr_src[p1] = sv.y;
        g_csr_src[p2] = sv.z;
        g_csr_src[p3] = sv.w;
    }
}

// ---------------- mma helper ----------------
__device__ __forceinline__ void mma16816(float* c, unsigned a0, unsigned a1,
                                         unsigned a2, unsigned a3,
                                         unsigned b0, unsigned b1) {
    asm volatile(
        "mma.sync.aligned.m16n8k16.row.col.f32.f16.f16.f32 "
        "{%0,%1,%2,%3}, {%4,%5,%6,%7}, {%8,%9}, {%0,%1,%2,%3};\n"
        : "+f"(c[0]), "+f"(c[1]), "+f"(c[2]), "+f"(c[3])
        : "r"(a0), "r"(a1), "r"(a2), "r"(a3), "r"(b0), "r"(b1));
}

// ---------------- xl/xr GEMM (tensor core): 128-row tiles, 256 threads ----------------
__global__ __launch_bounds__(256) void k_gemm_lr(
    int insel,
    const float* __restrict__ Wl, const float* __restrict__ Wr,
    const float* __restrict__ bl, const float* __restrict__ br)
{
    __shared__ __half As[128 * AS];
    __shared__ __half Bt[64 * BS];   // Bt[n_local][k]
    const __half* x = hin(insel);
    int tid = threadIdx.x, wid = tid >> 5, lane = tid & 31;
    int m0 = blockIdx.x * 128;
    int c0 = blockIdx.y * 64;
    bool isL = (c0 < HD);
    const float* W  = isL ? Wl : Wr;
    const float* bv = isL ? bl : br;
    int wc0 = c0 & (HD - 1);

    for (int i = tid; i < 1024; i += 256) {
        int r = i >> 3, c8 = i & 7;
        int row = m0 + r;
        uint4 v = make_uint4(0u, 0u, 0u, 0u);
        if (row < NNODES) v = ((const uint4*)x)[row * 8 + c8];
        *(uint4*)&As[r * AS + c8 * 8] = v;
    }
    for (int i = tid; i < 1024; i += 256) {
        int k = i >> 4, c4 = i & 15;
        float4 v = *(const float4*)&W[k * HD + wc0 + c4 * 4];
        Bt[(c4 * 4 + 0) * BS + k] = __float2half_rn(v.x);
        Bt[(c4 * 4 + 1) * BS + k] = __float2half_rn(v.y);
        Bt[(c4 * 4 + 2) * BS + k] = __float2half_rn(v.z);
        Bt[(c4 * 4 + 3) * BS + k] = __float2half_rn(v.w);
    }
    __syncthreads();

    float acc[8][4];
#pragma unroll
    for (int nt = 0; nt < 8; nt++)
#pragma unroll
        for (int j = 0; j < 4; j++) acc[nt][j] = 0.f;

    int r0 = wid * 16 + (lane >> 2);
    int kc = (lane & 3) * 2;
    int nb = lane >> 2;
#pragma unroll
    for (int ks = 0; ks < 4; ks++) {
        unsigned a0 = *(const unsigned*)&As[r0 * AS + ks * 16 + kc];
        unsigned a1 = *(const unsigned*)&As[(r0 + 8) * AS + ks * 16 + kc];
        unsigned a2 = *(const unsigned*)&As[r0 * AS + ks * 16 + kc + 8];
        unsigned a3 = *(const unsigned*)&As[(r0 + 8) * AS + ks * 16 + kc + 8];
#pragma unroll
        for (int nt = 0; nt < 8; nt++) {
            unsigned b0 = *(const unsigned*)&Bt[(nt * 8 + nb) * BS + ks * 16 + kc];
            unsigned b1 = *(const unsigned*)&Bt[(nt * 8 + nb) * BS + ks * 16 + kc + 8];
            mma16816(acc[nt], a0, a1, a2, a3, b0, b1);
        }
    }

    __half* out = isL ? g_xl : g_xr;
    int colb = (lane & 3) * 2;
    int rowA = m0 + wid * 16 + (lane >> 2);
#pragma unroll
    for (int nt = 0; nt < 8; nt++) {
        int c = wc0 + nt * 8 + colb;
        float bias0 = bv[c], bias1 = bv[c + 1];
        if (rowA < NNODES) {
            __half2 h = __floats2half2_rn(acc[nt][0] + bias0, acc[nt][1] + bias1);
            *(__half2*)&out[rowA * HD + c] = h;
        }
        if (rowA + 8 < NNODES) {
            __half2 h = __floats2half2_rn(acc[nt][2] + bias0, acc[nt][3] + bias1);
            *(__half2*)&out[(rowA + 8) * HD + c] = h;
        }
    }
}

// ---------------- GATv2 attention: 1 warp/node, 2 edge slots of 16 lanes (MLP=2) ----------------
__global__ void k_attn(const float* __restrict__ att, const float* __restrict__ bias,
                       int outsel)
{
    int n = (blockIdx.x * blockDim.x + threadIdx.x) >> 5;
    int lane = threadIdx.x & 31;
    if (n >= NNODES) return;
    int q = lane & 15, slot = lane >> 4;

    uint4 rr = ((const uint4*)g_xr)[n * 16 + q];
    __half2 r0 = *(__half2*)&rr.x, r1 = *(__half2*)&rr.y;
    __half2 r2 = *(__half2*)&rr.z, r3 = *(__half2*)&rr.w;

    float4 af0 = ((const float4*)att)[q * 2];
    float4 af1 = ((const float4*)att)[q * 2 + 1];
    __half2 a0 = __floats2half2_rn(af0.x, af0.y), a1 = __floats2half2_rn(af0.z, af0.w);
    __half2 a2 = __floats2half2_rn(af1.x, af1.y), a3 = __floats2half2_rn(af1.z, af1.w);
    const __half2 c02 = __floats2half2_rn(0.2f, 0.2f);

    float s = 0.f;
    float o0 = 0.f, o1 = 0.f, o2 = 0.f, o3 = 0.f, o4 = 0.f, o5 = 0.f, o6 = 0.f, o7 = 0.f;

    int beg = g_rowptr[n], end = g_rowptr[n + 1];
    int deg = end - beg;
    int niter = (deg + 3) >> 2;          // uniform across the warp

    for (int j = 0; j < niter; j++) {
        int p = beg + slot + j * 4;
        int eA = p, eB = p + 2;
        bool vA = eA < end, vB = eB < end;
        int sA = g_csr_src[vA ? eA : beg];
        int sB = g_csr_src[vB ? eB : beg];
        uint4 uA = ((const uint4*)g_xl)[sA * 16 + q];
        uint4 uB = ((const uint4*)g_xl)[sB * 16 + q];

#pragma unroll
        for (int ii = 0; ii < 2; ii++) {
            uint4 u = ii ? uB : uA;
            bool valid = ii ? vB : vA;
            __half2 v0 = *(__half2*)&u.x, v1 = *(__half2*)&u.y;
            __half2 v2 = *(__half2*)&u.z, v3 = *(__half2*)&u.w;

            __half2 e0 = __hadd2(v0, r0), e1 = __hadd2(v1, r1);
            __half2 e2 = __hadd2(v2, r2), e3 = __hadd2(v3, r3);
            __half2 l0 = __hmax2(e0, __hmul2(e0, c02));
            __half2 l1 = __hmax2(e1, __hmul2(e1, c02));
            __half2 l2 = __hmax2(e2, __hmul2(e2, c02));
            __half2 l3 = __hmax2(e3, __hmul2(e3, c02));
            __half2 d  = __hmul2(l0, a0);
            d = __hfma2(l1, a1, d);
            d = __hfma2(l2, a2, d);
            d = __hfma2(l3, a3, d);
            float part = __low2float(d) + __high2float(d);
            part += __shfl_xor_sync(0xffffffffu, part, 1);
            part += __shfl_xor_sync(0xffffffffu, part, 2);
            part += __shfl_xor_sync(0xffffffffu, part, 4);
            float w = valid ? __expf(part) : 0.f;
            s += w;
            float2 f0 = __half22float2(v0), f1 = __half22float2(v1);
            float2 f2 = __half22float2(v2), f3 = __half22float2(v3);
            o0 = fmaf(w, f0.x, o0); o1 = fmaf(w, f0.y, o1);
            o2 = fmaf(w, f1.x, o2); o3 = fmaf(w, f1.y, o3);
            o4 = fmaf(w, f2.x, o4); o5 = fmaf(w, f2.y, o5);
            o6 = fmaf(w, f3.x, o6); o7 = fmaf(w, f3.y, o7);
        }
    }

    s  += __shfl_xor_sync(0xffffffffu, s, 16);
    o0 += __shfl_xor_sync(0xffffffffu, o0, 16);
    o1 += __shfl_xor_sync(0xffffffffu, o1, 16);
    o2 += __shfl_xor_sync(0xffffffffu, o2, 16);
    o3 += __shfl_xor_sync(0xffffffffu, o3, 16);
    o4 += __shfl_xor_sync(0xffffffffu, o4, 16);
    o5 += __shfl_xor_sync(0xffffffffu, o5, 16);
    o6 += __shfl_xor_sync(0xffffffffu, o6, 16);
    o7 += __shfl_xor_sync(0xffffffffu, o7, 16);

    float inv = (deg > 0) ? (1.f / s) : 0.f;
    o0 *= inv; o1 *= inv; o2 *= inv; o3 *= inv;
    o4 *= inv; o5 *= inv; o6 *= inv; o7 *= inv;

    o0 = 0.5f * (o0 + __shfl_xor_sync(0xffffffffu, o0, 8));
    o1 = 0.5f * (o1 + __shfl_xor_sync(0xffffffffu, o1, 8));
    o2 = 0.5f * (o2 + __shfl_xor_sync(0xffffffffu, o2, 8));
    o3 = 0.5f * (o3 + __shfl_xor_sync(0xffffffffu, o3, 8));
    o4 = 0.5f * (o4 + __shfl_xor_sync(0xffffffffu, o4, 8));
    o5 = 0.5f * (o5 + __shfl_xor_sync(0xffffffffu, o5, 8));
    o6 = 0.5f * (o6 + __shfl_xor_sync(0xffffffffu, o6, 8));
    o7 = 0.5f * (o7 + __shfl_xor_sync(0xffffffffu, o7, 8));

    if (lane < 8) {
        float4 b0 = ((const float4*)bias)[q * 2];
        float4 b1 = ((const float4*)bias)[q * 2 + 1];
        float t0 = o0 + b0.x; t0 = t0 > 0.f ? t0 : 0.01f * t0;
        float t1 = o1 + b0.y; t1 = t1 > 0.f ? t1 : 0.01f * t1;
        float t2 = o2 + b0.z; t2 = t2 > 0.f ? t2 : 0.01f * t2;
        float t3 = o3 + b0.w; t3 = t3 > 0.f ? t3 : 0.01f * t3;
        float t4 = o4 + b1.x; t4 = t4 > 0.f ? t4 : 0.01f * t4;
        float t5 = o5 + b1.y; t5 = t5 > 0.f ? t5 : 0.01f * t5;
        float t6 = o6 + b1.z; t6 = t6 > 0.f ? t6 : 0.01f * t6;
        float t7 = o7 + b1.w; t7 = t7 > 0.f ? t7 : 0.01f * t7;
        __half2 h0 = __floats2half2_rn(t0, t1);
        __half2 h1 = __floats2half2_rn(t2, t3);
        __half2 h2 = __floats2half2_rn(t4, t5);
        __half2 h3 = __floats2half2_rn(t6, t7);
        uint4 pk;
        pk.x = *(unsigned*)&h0; pk.y = *(unsigned*)&h1;
        pk.z = *(unsigned*)&h2; pk.w = *(unsigned*)&h3;
        ((uint4*)hout(outsel))[n * 8 + q] = pk;
    }
}

// ---------------- final projection (tensor core): 128-row tiles, 256 threads ----------------
__global__ __launch_bounds__(256) void k_gemm_o(
    int insel,
    const float* __restrict__ Wo, const float* __restrict__ bo,
    float* __restrict__ out)
{
    __shared__ __half As[128 * AS];
    __shared__ __half Bt[64 * BS];
    const __half* x = hin(insel);
    int tid = threadIdx.x, wid = tid >> 5, lane = tid & 31;
    int m0 = blockIdx.x * 128;

    for (int i = tid; i < 1024; i += 256) {
        int r = i >> 3, c8 = i & 7;
        int row = m0 + r;
        uint4 v = make_uint4(0u, 0u, 0u, 0u);
        if (row < NNODES) v = ((const uint4*)x)[row * 8 + c8];
        *(uint4*)&As[r * AS + c8 * 8] = v;
    }
    for (int i = tid; i < 1024; i += 256) {
        int k = i >> 4, c4 = i & 15;
        float4 v = *(const float4*)&Wo[k * DD + c4 * 4];
        Bt[(c4 * 4 + 0) * BS + k] = __float2half_rn(v.x);
        Bt[(c4 * 4 + 1) * BS + k] = __float2half_rn(v.y);
        Bt[(c4 * 4 + 2) * BS + k] = __float2half_rn(v.z);
        Bt[(c4 * 4 + 3) * BS + k] = __float2half_rn(v.w);
    }
    __syncthreads();

    float acc[8][4];
#pragma unroll
    for (int nt = 0; nt < 8; nt++)
#pragma unroll
        for (int j = 0; j < 4; j++) acc[nt][j] = 0.f;

    int r0 = wid * 16 + (lane >> 2);
    int kc = (lane & 3) * 2;
    int nb = lane >> 2;
#pragma unroll
    for (int ks = 0; ks < 4; ks++) {
        unsigned a0 = *(const unsigned*)&As[r0 * AS + ks * 16 + kc];
        unsigned a1 = *(const unsigned*)&As[(r0 + 8) * AS + ks * 16 + kc];
        unsigned a2 = *(const unsigned*)&As[r0 * AS + ks * 16 + kc + 8];
        unsigned a3 = *(const unsigned*)&As[(r0 + 8) * AS + ks * 16 + kc + 8];
#pragma unroll
        for (int nt = 0; nt < 8; nt++) {
            unsigned b0 = *(const unsigned*)&Bt[(nt * 8 + nb) * BS + ks * 16 + kc];
            unsigned b1 = *(const unsigned*)&Bt[(nt * 8 + nb) * BS + ks * 16 + kc + 8];
            mma16816(acc[nt], a0, a1, a2, a3, b0, b1);
        }
    }

    int colb = (lane & 3) * 2;
    int rowA = m0 + wid * 16 + (lane >> 2);
#pragma unroll
    for (int nt = 0; nt < 8; nt++) {
        int c = nt * 8 + colb;
        float bias0 = bo[c], bias1 = bo[c + 1];
        if (rowA < NNODES) {
            float t0 = acc[nt][0] + bias0; t0 = t0 > 0.f ? t0 : 0.01f * t0;
            float t1 = acc[nt][1] + bias1; t1 = t1 > 0.f ? t1 : 0.01f * t1;
            *(float2*)&out[rowA * DD + c] = make_float2(t0, t1);
        }
        if (rowA + 8 < NNODES) {
            float t0 = acc[nt][2] + bias0; t0 = t0 > 0.f ? t0 : 0.01f * t0;
            float t1 = acc[nt][3] + bias1; t1 = t1 > 0.f ? t1 : 0.01f * t1;
            *(float2*)&out[(rowA + 8) * DD + c] = make_float2(t0, t1);
        }
    }
}

// ---------------- launch: CSR chain forked onto a side stream ----------------
extern "C" void kernel_launch(void* const* d_in, const int* in_sizes, int n_in,
                              void* d_out, int out_size)
{
    const int*   ei   = (const int*)d_in[0];
    const float* pert = (const float*)d_in[2];
    const float* Wl   = (const float*)d_in[3];
    const float* bl   = (const float*)d_in[4];
    const float* Wr   = (const float*)d_in[5];
    const float* br   = (const float*)d_in[6];
    const float* att  = (const float*)d_in[7];
    const float* bias = (const float*)d_in[8];
    const float* Wo   = (const float*)d_in[9];
    const float* bo   = (const float*)d_in[10];
    float* out = (float*)d_out;

    const int* src = ei;
    const int* dst = ei + NEDGES;

    // fork: CSR chain on side stream, cvt+layer0-GEMM on main stream
    cudaStream_t s2;
    cudaStreamCreateWithFlags(&s2, cudaStreamNonBlocking);
    cudaEvent_t evFork, evJoin;
    cudaEventCreateWithFlags(&evFork, cudaEventDisableTiming);
    cudaEventCreateWithFlags(&evJoin, cudaEventDisableTiming);

    cudaEventRecord(evFork, 0);
    cudaStreamWaitEvent(s2, evFork, 0);

    // side stream: CSR build
    k_hist<<<(NEDGES / 4 + 255) / 256, 256, 0, s2>>>(dst);
    k_scan_part<<<NPART, 1024, 0, s2>>>();
    k_scan_add<<<NPART, 1024, 0, s2>>>();
    k_scatter<<<(NEDGES / 4 + 255) / 256, 256, 0, s2>>>(src, dst);
    cudaEventRecord(evJoin, s2);

    // main stream: cvt + layer-0 GEMM (independent of CSR)
    k_cvt<<<(NNODES * 16 + 255) / 256, 256>>>(pert);
    {
        dim3 g((NNODES + 127) / 128, 4);
        k_gemm_lr<<<g, 256>>>(0,
                              Wl, Wr, bl, br);
    }
    // join before attention needs the CSR
    cudaStreamWaitEvent(0, evJoin, 0);

    for (int l = 0; l < LL; l++) {
        int insel  = (l & 1);        // 0 = g_xa, 1 = g_xb
        int outsel = insel ^ 1;
        if (l > 0) {
            dim3 g((NNODES + 127) / 128, 4);
            k_gemm_lr<<<g, 256>>>(insel,
                                  Wl + (size_t)l * DD * HD, Wr + (size_t)l * DD * HD,
                                  bl + (size_t)l * HD,      br + (size_t)l * HD);
        }
        k_attn<<<(NNODES * 32 + 255) / 256, 256>>>(att + (size_t)l * HD,
                                                   bias + (size_t)l * DD, outsel);
    }
    // after 4 layers the last output landed in g_xa (layer 3: insel=1 -> outsel=0)
    k_gemm_o<<<(NNODES + 127) / 128, 256>>>(0, Wo, bo, out);
    // streams/events intentionally not destroyed: kernel_launch is invoked only
    // a couple of times (correctness + capture); destroying a stream that is part
    // of an ongoing capture would invalidate the capture.
}